// round 15
// baseline (speedup 1.0000x reference)
#include <cuda_runtime.h>
#include <cuda_bf16.h>

#define BS   128
#define OBJ  512
#define RNN  1024
#define HID  512
#define KCHUNKS 16   // k-chunks of 64

// GEMM partials, layout [chunk][hid][bs] -> coalesced stores. 4MB, L2-resident.
__device__ float g_part[KCHUNKS * HID * BS];
// Reduced att_h + bias, TRANSPOSED layout [bs][hid] (256KB, L2-resident).
__device__ float g_attht[BS * HID];
// Masked un-normalized exp values + per-(row,chunk) partial sums.
__device__ float g_e[BS * OBJ];
__device__ float g_psum[BS * 4];

__device__ __forceinline__ float tanh_fast(float x) {
    float y;
    asm("tanh.approx.f32 %0, %1;" : "=f"(y) : "f"(x));
    return y;
}

// ---------------- GEMM: att_h partials (R11-proven, unchanged) --------------
__global__ __launch_bounds__(256) void gemm_kernel(
    const float* __restrict__ h, const float* __restrict__ W)
{
    __shared__ float h_s[32][129];   // [k][b]
    __shared__ float w_s[32][68];    // [k][n], pitch 68
    const int n0 = blockIdx.x * 64;
    const int k0 = blockIdx.y * 64;
    const int t  = threadIdx.x;
    const int tm = t & 31;
    const int tn = t >> 5;
    const int hb = t >> 3, hk = t & 7;
    const int wr = t >> 3, wk = t & 7;

    float4 hv[4], wv[2];
    #pragma unroll
    for (int r = 0; r < 4; ++r)
        hv[r] = *(const float4*)(h + (hb + 32 * r) * RNN + k0 + hk * 4);
    #pragma unroll
    for (int r = 0; r < 2; ++r)
        wv[r] = *(const float4*)(W + (n0 + wr + 32 * r) * RNN + k0 + wk * 4);

    #pragma unroll
    for (int r = 0; r < 4; ++r) {
        h_s[hk*4+0][hb + 32*r] = hv[r].x; h_s[hk*4+1][hb + 32*r] = hv[r].y;
        h_s[hk*4+2][hb + 32*r] = hv[r].z; h_s[hk*4+3][hb + 32*r] = hv[r].w;
    }
    #pragma unroll
    for (int r = 0; r < 2; ++r) {
        w_s[wk*4+0][wr + 32*r] = wv[r].x; w_s[wk*4+1][wr + 32*r] = wv[r].y;
        w_s[wk*4+2][wr + 32*r] = wv[r].z; w_s[wk*4+3][wr + 32*r] = wv[r].w;
    }
    __syncthreads();

    float4 hv2[4], wv2[2];
    #pragma unroll
    for (int r = 0; r < 4; ++r)
        hv2[r] = *(const float4*)(h + (hb + 32 * r) * RNN + k0 + 32 + hk * 4);
    #pragma unroll
    for (int r = 0; r < 2; ++r)
        wv2[r] = *(const float4*)(W + (n0 + wr + 32 * r) * RNN + k0 + 32 + wk * 4);

    float acc[4][8] = {};
    #pragma unroll 4
    for (int k = 0; k < 32; ++k) {
        float a0 = h_s[k][tm],      a1 = h_s[k][tm + 32],
              a2 = h_s[k][tm + 64], a3 = h_s[k][tm + 96];
        float4 b0 = *(const float4*)&w_s[k][tn * 8];
        float4 b1 = *(const float4*)&w_s[k][tn * 8 + 4];
        float bb[8] = {b0.x, b0.y, b0.z, b0.w, b1.x, b1.y, b1.z, b1.w};
        #pragma unroll
        for (int j = 0; j < 8; ++j) {
            acc[0][j] += a0 * bb[j];
            acc[1][j] += a1 * bb[j];
            acc[2][j] += a2 * bb[j];
            acc[3][j] += a3 * bb[j];
        }
    }
    __syncthreads();

    #pragma unroll
    for (int r = 0; r < 4; ++r) {
        h_s[hk*4+0][hb + 32*r] = hv2[r].x; h_s[hk*4+1][hb + 32*r] = hv2[r].y;
        h_s[hk*4+2][hb + 32*r] = hv2[r].z; h_s[hk*4+3][hb + 32*r] = hv2[r].w;
    }
    #pragma unroll
    for (int r = 0; r < 2; ++r) {
        w_s[wk*4+0][wr + 32*r] = wv2[r].x; w_s[wk*4+1][wr + 32*r] = wv2[r].y;
        w_s[wk*4+2][wr + 32*r] = wv2[r].z; w_s[wk*4+3][wr + 32*r] = wv2[r].w;
    }
    __syncthreads();

    #pragma unroll 4
    for (int k = 0; k < 32; ++k) {
        float a0 = h_s[k][tm],      a1 = h_s[k][tm + 32],
              a2 = h_s[k][tm + 64], a3 = h_s[k][tm + 96];
        float4 b0 = *(const float4*)&w_s[k][tn * 8];
        float4 b1 = *(const float4*)&w_s[k][tn * 8 + 4];
        float bb[8] = {b0.x, b0.y, b0.z, b0.w, b1.x, b1.y, b1.z, b1.w};
        #pragma unroll
        for (int j = 0; j < 8; ++j) {
            acc[0][j] += a0 * bb[j];
            acc[1][j] += a1 * bb[j];
            acc[2][j] += a2 * bb[j];
            acc[3][j] += a3 * bb[j];
        }
    }

    float* outp = g_part + blockIdx.y * (HID * BS);
    #pragma unroll
    for (int j = 0; j < 8; ++j)
        #pragma unroll
        for (int i = 0; i < 4; ++i)
            outp[(n0 + tn * 8 + j) * BS + tm + 32*i] = acc[i][j];
}

// ---------------- Reduce (PDL) + transpose (R14-proven) ----------------
__global__ __launch_bounds__(1024) void reduce_kernel(
    const float* __restrict__ b_h2att)
{
    __shared__ float tile[8][132];
    const int t  = threadIdx.x;
    const int n0 = blockIdx.x * 8;
    const int nl = t >> 7;            // 0..7
    const int b  = t & 127;

    float bias = b_h2att[n0 + nl];    // independent of gemm
    cudaGridDependencySynchronize();  // wait for gemm grid

    float s = bias;
    #pragma unroll
    for (int c = 0; c < KCHUNKS; ++c)
        s += g_part[c * (HID * BS) + (n0 + nl) * BS + b];
    tile[nl][b] = s;
    __syncthreads();

    const int b2 = t >> 3;            // 0..127
    const int n2 = t & 7;             // 0..7
    g_attht[b2 * HID + n0 + n2] = tile[n2][b2];
}

// ---------------- Scores (PDL): deep prefetch + masked exp + psums ----------
// grid 512 (= 128 b x 4 obj-chunks of 128), 256 threads. 3 of 8 iterations
// (24 float4/thread) prefetched into registers BEFORE the grid sync ->
// ~50MB of the stream overlaps the otherwise DRAM-idle gemm phase.
// Max-free softmax (|score| <= ||w_alpha||_1, validated R8/R9).
__global__ __launch_bounds__(256) void scores_kernel(
    const float* __restrict__ att_feats,
    const float* __restrict__ w_alpha,
    const int*   __restrict__ att_masks)
{
    const int b     = blockIdx.x >> 2;
    const int chunk = blockIdx.x & 3;
    __shared__ float ah[HID];
    __shared__ float wa[HID];
    __shared__ float mf[128];
    __shared__ float wsum[8];
    const int t = threadIdx.x;
    const int w = t >> 5, lane = t & 31;

    const float4* base = (const float4*)(att_feats
                         + (size_t)b * OBJ * HID + (size_t)chunk * 128 * HID);

    // ---- producer-independent prefetches (overlap gemm + reduce) ----
    float wv0 = w_alpha[t], wv1 = w_alpha[t + 256];
    float mv = (t < 128) ? (float)att_masks[b * OBJ + chunk * 128 + t] : 0.f;
    float4 pA0[4], pA1[4], pB0[4], pB1[4], pC0[4], pC1[4];
    {
        const float4* rA0 = base + (w)      * (HID / 4);
        const float4* rA1 = base + (w + 8)  * (HID / 4);
        const float4* rB0 = base + (w + 16) * (HID / 4);
        const float4* rB1 = base + (w + 24) * (HID / 4);
        const float4* rC0 = base + (w + 32) * (HID / 4);
        const float4* rC1 = base + (w + 40) * (HID / 4);
        #pragma unroll
        for (int i = 0; i < 4; ++i) {
            pA0[i] = __ldcs(rA0 + lane + 32 * i);
            pA1[i] = __ldcs(rA1 + lane + 32 * i);
            pB0[i] = __ldcs(rB0 + lane + 32 * i);
            pB1[i] = __ldcs(rB1 + lane + 32 * i);
            pC0[i] = __ldcs(rC0 + lane + 32 * i);
            pC1[i] = __ldcs(rC1 + lane + 32 * i);
        }
    }

    cudaGridDependencySynchronize();           // wait for reduce grid

    wa[t] = wv0; wa[t + 256] = wv1;
    if (t < 128) mf[t] = mv;
    ah[t]       = g_attht[b * HID + t];        // 2KB contiguous, L2-resident
    ah[t + 256] = g_attht[b * HID + t + 256];
    __syncthreads();

    const float4* ah4 = (const float4*)ah;
    const float4* wa4 = (const float4*)wa;

    float esum = 0.f;   // meaningful on lane 0 of each warp

    // ---- process the 3 prefetched iteration-pairs ----
    #pragma unroll
    for (int pi = 0; pi < 3; ++pi) {
        float4 *f0, *f1;
        int o;
        if (pi == 0)      { f0 = pA0; f1 = pA1; o = w; }
        else if (pi == 1) { f0 = pB0; f1 = pB1; o = w + 16; }
        else              { f0 = pC0; f1 = pC1; o = w + 32; }
        float s0 = 0.f, s1 = 0.f;
        #pragma unroll
        for (int i = 0; i < 4; ++i) {
            int idx = lane + 32 * i;
            float4 a  = ah4[idx];
            float4 wv = wa4[idx];
            s0 += tanh_fast(f0[i].x + a.x) * wv.x;
            s0 += tanh_fast(f0[i].y + a.y) * wv.y;
            s0 += tanh_fast(f0[i].z + a.z) * wv.z;
            s0 += tanh_fast(f0[i].w + a.w) * wv.w;
            s1 += tanh_fast(f1[i].x + a.x) * wv.x;
            s1 += tanh_fast(f1[i].y + a.y) * wv.y;
            s1 += tanh_fast(f1[i].z + a.z) * wv.z;
            s1 += tanh_fast(f1[i].w + a.w) * wv.w;
        }
        #pragma unroll
        for (int d = 16; d; d >>= 1) {
            s0 += __shfl_xor_sync(0xffffffffu, s0, d);
            s1 += __shfl_xor_sync(0xffffffffu, s1, d);
        }
        if (lane == 0) {
            float e0 = mf[o]     * __expf(s0);
            float e1 = mf[o + 8] * __expf(s1);
            g_e[b * OBJ + chunk * 128 + o]     = e0;
            g_e[b * OBJ + chunk * 128 + o + 8] = e1;
            esum += e0 + e1;
        }
    }

    // ---- remaining 5 iterations ----
    for (int o = w + 48; o < 128; o += 16) {
        const float4* r0 = base + o       * (HID / 4);
        const float4* r1 = base + (o + 8) * (HID / 4);
        float4 f0[4], f1[4];
        #pragma unroll
        for (int i = 0; i < 4; ++i) {
            f0[i] = __ldcs(r0 + lane + 32 * i);
            f1[i] = __ldcs(r1 + lane + 32 * i);
        }
        float s0 = 0.f, s1 = 0.f;
        #pragma unroll
        for (int i = 0; i < 4; ++i) {
            int idx = lane + 32 * i;
            float4 a  = ah4[idx];
            float4 wv = wa4[idx];
            s0 += tanh_fast(f0[i].x + a.x) * wv.x;
            s0 += tanh_fast(f0[i].y + a.y) * wv.y;
            s0 += tanh_fast(f0[i].z + a.z) * wv.z;
            s0 += tanh_fast(f0[i].w + a.w) * wv.w;
            s1 += tanh_fast(f1[i].x + a.x) * wv.x;
            s1 += tanh_fast(f1[i].y + a.y) * wv.y;
            s1 += tanh_fast(f1[i].z + a.z) * wv.z;
            s1 += tanh_fast(f1[i].w + a.w) * wv.w;
        }
        #pragma unroll
        for (int d = 16; d; d >>= 1) {
            s0 += __shfl_xor_sync(0xffffffffu, s0, d);
            s1 += __shfl_xor_sync(0xffffffffu, s1, d);
        }
        if (lane == 0) {
            float e0 = mf[o]     * __expf(s0);
            float e1 = mf[o + 8] * __expf(s1);
            g_e[b * OBJ + chunk * 128 + o]     = e0;
            g_e[b * OBJ + chunk * 128 + o + 8] = e1;
            esum += e0 + e1;
        }
    }

    if (lane == 0) wsum[w] = esum;
    __syncthreads();
    if (t == 0) {
        float p = 0.f;
        #pragma unroll
        for (int i = 0; i < 8; ++i) p += wsum[i];   // fixed order: deterministic
        g_psum[b * 4 + chunk] = p;
    }
}

// ---------------- Normalize (PDL): no reductions, no chains ----------------
__global__ __launch_bounds__(128) void normalize_kernel(float* __restrict__ out)
{
    const int b = blockIdx.x;
    const int t = threadIdx.x;
    cudaGridDependencySynchronize();           // wait for scores grid
    const float inv = 1.f / (g_psum[b*4+0] + g_psum[b*4+1]
                           + g_psum[b*4+2] + g_psum[b*4+3]);
    float4 e = ((const float4*)g_e)[b * (OBJ/4) + t];
    float4 o = make_float4(e.x * inv, e.y * inv, e.z * inv, e.w * inv);
    ((float4*)out)[b * (OBJ/4) + t] = o;
}

static void launch_pdl(void* func, dim3 grid, dim3 block, void** args) {
    cudaLaunchConfig_t cfg = {};
    cfg.gridDim = grid;
    cfg.blockDim = block;
    cfg.dynamicSmemBytes = 0;
    cfg.stream = 0;
    cudaLaunchAttribute attr[1];
    attr[0].id = cudaLaunchAttributeProgrammaticStreamSerialization;
    attr[0].val.programmaticStreamSerializationAllowed = 1;
    cfg.attrs = attr;
    cfg.numAttrs = 1;
    cudaLaunchKernelExC(&cfg, func, args);
}

extern "C" void kernel_launch(void* const* d_in, const int* in_sizes, int n_in,
                              void* d_out, int out_size) {
    const float* h         = (const float*)d_in[0];
    const float* att_feats = (const float*)d_in[1];
    const int*   att_masks = (const int*)  d_in[2];
    const float* W_h2att   = (const float*)d_in[3];
    const float* b_h2att   = (const float*)d_in[4];
    const float* w_alpha   = (const float*)d_in[5];
    // d_in[6] = b_alpha: cancels in softmax, unused.
    float* out = (float*)d_out;

    gemm_kernel<<<dim3(8, 16), 256>>>(h, W_h2att);

    {   // reduce + transpose (PDL)
        void* args[] = {(void*)&b_h2att};
        launch_pdl((void*)reduce_kernel, dim3(64), dim3(1024), args);
    }
    {   // scores (PDL)
        void* args[] = {(void*)&att_feats, (void*)&w_alpha, (void*)&att_masks};
        launch_pdl((void*)scores_kernel, dim3(512), dim3(256), args);
    }
    {   // normalize (PDL)
        void* args[] = {(void*)&out};
        launch_pdl((void*)normalize_kernel, dim3(BS), dim3(128), args);
    }
}

// round 16
// speedup vs baseline: 1.0576x; 1.0576x over previous
#include <cuda_runtime.h>
#include <cuda_bf16.h>

#define BS   128
#define OBJ  512
#define RNN  1024
#define HID  512
#define KCHUNKS 16   // k-chunks of 64

// GEMM partials, layout [chunk][hid][bs] -> coalesced stores. 4MB, L2-resident.
__device__ float g_part[KCHUNKS * HID * BS];
// Reduced att_h + bias, TRANSPOSED layout [bs][hid] (256KB, L2-resident).
__device__ float g_attht[BS * HID];
// Masked un-normalized exp values + per-(row,chunk) partial sums.
__device__ float g_e[BS * OBJ];
__device__ float g_psum[BS * 4];

__device__ __forceinline__ float tanh_fast(float x) {
    float y;
    asm("tanh.approx.f32 %0, %1;" : "=f"(y) : "f"(x));
    return y;
}

// Pack a scalar into both halves of an fp32x2 register pair.
__device__ __forceinline__ unsigned long long pack2(float x) {
    unsigned long long r;
    asm("mov.b64 %0, {%1, %1};" : "=l"(r) : "f"(x));
    return r;
}
// d = a * b + d on packed fp32x2 (exact per-lane fp32 FMA).
__device__ __forceinline__ void ffma2(unsigned long long& d,
                                      unsigned long long a,
                                      unsigned long long b) {
    asm("fma.rn.f32x2 %0, %1, %2, %0;" : "+l"(d) : "l"(a), "l"(b));
}

// ---------------- GEMM: att_h partials (R11 shape, f32x2 core) --------------
// grid (8 n-tiles of 64, 16 k-chunks of 64) = 128 blocks = one wave.
// 256 threads; per-thread 4b x 8n held as 4x4 packed fp32x2 accumulators.
// Inner iter: 4 LDS.32 (a) + 4 MOV64 (dup) + 2 LDS.128 (packed b) + 16 FFMA2
// -> half the FFMA issue slots of the scalar version.
__global__ __launch_bounds__(256) void gemm_kernel(
    const float* __restrict__ h, const float* __restrict__ W)
{
    __shared__ float h_s[32][129];   // [k][b]
    __shared__ float w_s[32][68];    // [k][n], pitch 68 floats (16B-aligned)
    const int n0 = blockIdx.x * 64;
    const int k0 = blockIdx.y * 64;
    const int t  = threadIdx.x;
    const int tm = t & 31;
    const int tn = t >> 5;
    const int hb = t >> 3, hk = t & 7;
    const int wr = t >> 3, wk = t & 7;

    float4 hv[4], wv[2];
    #pragma unroll
    for (int r = 0; r < 4; ++r)
        hv[r] = *(const float4*)(h + (hb + 32 * r) * RNN + k0 + hk * 4);
    #pragma unroll
    for (int r = 0; r < 2; ++r)
        wv[r] = *(const float4*)(W + (n0 + wr + 32 * r) * RNN + k0 + wk * 4);

    #pragma unroll
    for (int r = 0; r < 4; ++r) {
        h_s[hk*4+0][hb + 32*r] = hv[r].x; h_s[hk*4+1][hb + 32*r] = hv[r].y;
        h_s[hk*4+2][hb + 32*r] = hv[r].z; h_s[hk*4+3][hb + 32*r] = hv[r].w;
    }
    #pragma unroll
    for (int r = 0; r < 2; ++r) {
        w_s[wk*4+0][wr + 32*r] = wv[r].x; w_s[wk*4+1][wr + 32*r] = wv[r].y;
        w_s[wk*4+2][wr + 32*r] = wv[r].z; w_s[wk*4+3][wr + 32*r] = wv[r].w;
    }
    __syncthreads();

    float4 hv2[4], wv2[2];
    #pragma unroll
    for (int r = 0; r < 4; ++r)
        hv2[r] = *(const float4*)(h + (hb + 32 * r) * RNN + k0 + 32 + hk * 4);
    #pragma unroll
    for (int r = 0; r < 2; ++r)
        wv2[r] = *(const float4*)(W + (n0 + wr + 32 * r) * RNN + k0 + 32 + wk * 4);

    unsigned long long acc[4][4] = {};   // [b_comp][n_pair], fp32x2 packed

    #pragma unroll 4
    for (int k = 0; k < 32; ++k) {
        unsigned long long pa0 = pack2(h_s[k][tm]);
        unsigned long long pa1 = pack2(h_s[k][tm + 32]);
        unsigned long long pa2 = pack2(h_s[k][tm + 64]);
        unsigned long long pa3 = pack2(h_s[k][tm + 96]);
        ulonglong2 q0 = *(const ulonglong2*)&w_s[k][tn * 8];      // (n0n1,n2n3)
        ulonglong2 q1 = *(const ulonglong2*)&w_s[k][tn * 8 + 4];  // (n4n5,n6n7)
        unsigned long long pb[4] = {q0.x, q0.y, q1.x, q1.y};
        #pragma unroll
        for (int j = 0; j < 4; ++j) {
            ffma2(acc[0][j], pa0, pb[j]);
            ffma2(acc[1][j], pa1, pb[j]);
            ffma2(acc[2][j], pa2, pb[j]);
            ffma2(acc[3][j], pa3, pb[j]);
        }
    }
    __syncthreads();

    #pragma unroll
    for (int r = 0; r < 4; ++r) {
        h_s[hk*4+0][hb + 32*r] = hv2[r].x; h_s[hk*4+1][hb + 32*r] = hv2[r].y;
        h_s[hk*4+2][hb + 32*r] = hv2[r].z; h_s[hk*4+3][hb + 32*r] = hv2[r].w;
    }
    #pragma unroll
    for (int r = 0; r < 2; ++r) {
        w_s[wk*4+0][wr + 32*r] = wv2[r].x; w_s[wk*4+1][wr + 32*r] = wv2[r].y;
        w_s[wk*4+2][wr + 32*r] = wv2[r].z; w_s[wk*4+3][wr + 32*r] = wv2[r].w;
    }
    __syncthreads();

    #pragma unroll 4
    for (int k = 0; k < 32; ++k) {
        unsigned long long pa0 = pack2(h_s[k][tm]);
        unsigned long long pa1 = pack2(h_s[k][tm + 32]);
        unsigned long long pa2 = pack2(h_s[k][tm + 64]);
        unsigned long long pa3 = pack2(h_s[k][tm + 96]);
        ulonglong2 q0 = *(const ulonglong2*)&w_s[k][tn * 8];
        ulonglong2 q1 = *(const ulonglong2*)&w_s[k][tn * 8 + 4];
        unsigned long long pb[4] = {q0.x, q0.y, q1.x, q1.y};
        #pragma unroll
        for (int j = 0; j < 4; ++j) {
            ffma2(acc[0][j], pa0, pb[j]);
            ffma2(acc[1][j], pa1, pb[j]);
            ffma2(acc[2][j], pa2, pb[j]);
            ffma2(acc[3][j], pa3, pb[j]);
        }
    }

    // Coalesced epilogue: unpack; per (j,half,i) lanes write consecutive b.
    float* outp = g_part + blockIdx.y * (HID * BS);
    #pragma unroll
    for (int j = 0; j < 4; ++j) {
        #pragma unroll
        for (int i = 0; i < 4; ++i) {
            float lo, hi;
            asm("mov.b64 {%0, %1}, %2;" : "=f"(lo), "=f"(hi) : "l"(acc[i][j]));
            outp[(n0 + tn * 8 + 2*j)     * BS + tm + 32*i] = lo;
            outp[(n0 + tn * 8 + 2*j + 1) * BS + tm + 32*i] = hi;
        }
    }
}

// ---------------- Reduce (PDL) + transpose (R14-proven) ----------------
__global__ __launch_bounds__(1024) void reduce_kernel(
    const float* __restrict__ b_h2att)
{
    __shared__ float tile[8][132];
    const int t  = threadIdx.x;
    const int n0 = blockIdx.x * 8;
    const int nl = t >> 7;            // 0..7
    const int b  = t & 127;

    float bias = b_h2att[n0 + nl];    // independent of gemm
    cudaGridDependencySynchronize();  // wait for gemm grid

    float s = bias;
    #pragma unroll
    for (int c = 0; c < KCHUNKS; ++c)
        s += g_part[c * (HID * BS) + (n0 + nl) * BS + b];
    tile[nl][b] = s;
    __syncthreads();

    const int b2 = t >> 3;            // 0..127
    const int n2 = t & 7;             // 0..7
    g_attht[b2 * HID + n0 + n2] = tile[n2][b2];
}

// ---------------- Scores (PDL): masked exp + chunk psums (R14-proven) -------
// grid 512 (= 128 b x 4 obj-chunks of 128), 256 threads. Max-free softmax
// (|score| <= ||w_alpha||_1 ~ 18, validated R8/R9/R14). 1-iter prefetch.
__global__ __launch_bounds__(256) void scores_kernel(
    const float* __restrict__ att_feats,
    const float* __restrict__ w_alpha,
    const int*   __restrict__ att_masks)
{
    const int b     = blockIdx.x >> 2;
    const int chunk = blockIdx.x & 3;
    __shared__ float ah[HID];
    __shared__ float wa[HID];
    __shared__ float mf[128];
    __shared__ float wsum[8];
    const int t = threadIdx.x;
    const int w = t >> 5, lane = t & 31;

    const float4* base = (const float4*)(att_feats
                         + (size_t)b * OBJ * HID + (size_t)chunk * 128 * HID);

    // ---- producer-independent prefetches (overlap gemm + reduce) ----
    float wv0 = w_alpha[t], wv1 = w_alpha[t + 256];
    float mv = (t < 128) ? (float)att_masks[b * OBJ + chunk * 128 + t] : 0.f;
    float4 p0[4], p1[4];                       // peeled iter (o = w)
    {
        const float4* r0 = base + w       * (HID / 4);
        const float4* r1 = base + (w + 8) * (HID / 4);
        #pragma unroll
        for (int i = 0; i < 4; ++i) {
            p0[i] = __ldcs(r0 + lane + 32 * i);
            p1[i] = __ldcs(r1 + lane + 32 * i);
        }
    }

    cudaGridDependencySynchronize();           // wait for reduce grid

    wa[t] = wv0; wa[t + 256] = wv1;
    if (t < 128) mf[t] = mv;
    ah[t]       = g_attht[b * HID + t];        // 2KB contiguous, L2-resident
    ah[t + 256] = g_attht[b * HID + t + 256];
    __syncthreads();

    const float4* ah4 = (const float4*)ah;
    const float4* wa4 = (const float4*)wa;

    float esum = 0.f;   // meaningful on lane 0 of each warp

    // ---- peeled first iteration ----
    {
        float s0 = 0.f, s1 = 0.f;
        #pragma unroll
        for (int i = 0; i < 4; ++i) {
            int idx = lane + 32 * i;
            float4 a  = ah4[idx];
            float4 wv = wa4[idx];
            s0 += tanh_fast(p0[i].x + a.x) * wv.x;
            s0 += tanh_fast(p0[i].y + a.y) * wv.y;
            s0 += tanh_fast(p0[i].z + a.z) * wv.z;
            s0 += tanh_fast(p0[i].w + a.w) * wv.w;
            s1 += tanh_fast(p1[i].x + a.x) * wv.x;
            s1 += tanh_fast(p1[i].y + a.y) * wv.y;
            s1 += tanh_fast(p1[i].z + a.z) * wv.z;
            s1 += tanh_fast(p1[i].w + a.w) * wv.w;
        }
        #pragma unroll
        for (int d = 16; d; d >>= 1) {
            s0 += __shfl_xor_sync(0xffffffffu, s0, d);
            s1 += __shfl_xor_sync(0xffffffffu, s1, d);
        }
        if (lane == 0) {
            float e0 = mf[w]     * __expf(s0);
            float e1 = mf[w + 8] * __expf(s1);
            g_e[b * OBJ + chunk * 128 + w]     = e0;
            g_e[b * OBJ + chunk * 128 + w + 8] = e1;
            esum += e0 + e1;
        }
    }

    // ---- remaining iterations ----
    for (int o = w + 16; o < 128; o += 16) {
        const float4* r0 = base + o       * (HID / 4);
        const float4* r1 = base + (o + 8) * (HID / 4);
        float4 f0[4], f1[4];
        #pragma unroll
        for (int i = 0; i < 4; ++i) {
            f0[i] = __ldcs(r0 + lane + 32 * i);
            f1[i] = __ldcs(r1 + lane + 32 * i);
        }
        float s0 = 0.f, s1 = 0.f;
        #pragma unroll
        for (int i = 0; i < 4; ++i) {
            int idx = lane + 32 * i;
            float4 a  = ah4[idx];
            float4 wv = wa4[idx];
            s0 += tanh_fast(f0[i].x + a.x) * wv.x;
            s0 += tanh_fast(f0[i].y + a.y) * wv.y;
            s0 += tanh_fast(f0[i].z + a.z) * wv.z;
            s0 += tanh_fast(f0[i].w + a.w) * wv.w;
            s1 += tanh_fast(f1[i].x + a.x) * wv.x;
            s1 += tanh_fast(f1[i].y + a.y) * wv.y;
            s1 += tanh_fast(f1[i].z + a.z) * wv.z;
            s1 += tanh_fast(f1[i].w + a.w) * wv.w;
        }
        #pragma unroll
        for (int d = 16; d; d >>= 1) {
            s0 += __shfl_xor_sync(0xffffffffu, s0, d);
            s1 += __shfl_xor_sync(0xffffffffu, s1, d);
        }
        if (lane == 0) {
            float e0 = mf[o]     * __expf(s0);
            float e1 = mf[o + 8] * __expf(s1);
            g_e[b * OBJ + chunk * 128 + o]     = e0;
            g_e[b * OBJ + chunk * 128 + o + 8] = e1;
            esum += e0 + e1;
        }
    }

    if (lane == 0) wsum[w] = esum;
    __syncthreads();
    if (t == 0) {
        float p = 0.f;
        #pragma unroll
        for (int i = 0; i < 8; ++i) p += wsum[i];   // fixed order: deterministic
        g_psum[b * 4 + chunk] = p;
    }
}

// ---------------- Normalize (PDL): no reductions, no chains ----------------
__global__ __launch_bounds__(128) void normalize_kernel(float* __restrict__ out)
{
    const int b = blockIdx.x;
    const int t = threadIdx.x;
    cudaGridDependencySynchronize();           // wait for scores grid
    const float inv = 1.f / (g_psum[b*4+0] + g_psum[b*4+1]
                           + g_psum[b*4+2] + g_psum[b*4+3]);
    float4 e = ((const float4*)g_e)[b * (OBJ/4) + t];
    float4 o = make_float4(e.x * inv, e.y * inv, e.z * inv, e.w * inv);
    ((float4*)out)[b * (OBJ/4) + t] = o;
}

static void launch_pdl(void* func, dim3 grid, dim3 block, void** args) {
    cudaLaunchConfig_t cfg = {};
    cfg.gridDim = grid;
    cfg.blockDim = block;
    cfg.dynamicSmemBytes = 0;
    cfg.stream = 0;
    cudaLaunchAttribute attr[1];
    attr[0].id = cudaLaunchAttributeProgrammaticStreamSerialization;
    attr[0].val.programmaticStreamSerializationAllowed = 1;
    cfg.attrs = attr;
    cfg.numAttrs = 1;
    cudaLaunchKernelExC(&cfg, func, args);
}

extern "C" void kernel_launch(void* const* d_in, const int* in_sizes, int n_in,
                              void* d_out, int out_size) {
    const float* h         = (const float*)d_in[0];
    const float* att_feats = (const float*)d_in[1];
    const int*   att_masks = (const int*)  d_in[2];
    const float* W_h2att   = (const float*)d_in[3];
    const float* b_h2att   = (const float*)d_in[4];
    const float* w_alpha   = (const float*)d_in[5];
    // d_in[6] = b_alpha: cancels in softmax, unused.
    float* out = (float*)d_out;

    gemm_kernel<<<dim3(8, 16), 256>>>(h, W_h2att);

    {   // reduce + transpose (PDL)
        void* args[] = {(void*)&b_h2att};
        launch_pdl((void*)reduce_kernel, dim3(64), dim3(1024), args);
    }
    {   // scores (PDL)
        void* args[] = {(void*)&att_feats, (void*)&w_alpha, (void*)&att_masks};
        launch_pdl((void*)scores_kernel, dim3(512), dim3(256), args);
    }
    {   // normalize (PDL)
        void* args[] = {(void*)&out};
        launch_pdl((void*)normalize_kernel, dim3(BS), dim3(128), args);
    }
}

// round 17
// speedup vs baseline: 1.0849x; 1.0258x over previous
#include <cuda_runtime.h>
#include <cuda_bf16.h>
#include <cstdint>

#define BS   128
#define OBJ  512
#define RNN  1024
#define HID  512
#define KCHUNKS 8    // k-chunks of 128

// GEMM partials, layout [chunk][hid][bs]. 2MB, L2-resident.
__device__ float g_part[KCHUNKS * HID * BS];
// Reduced att_h + bias, TRANSPOSED layout [bs][hid] (256KB, L2-resident).
__device__ float g_attht[BS * HID];
// Masked un-normalized exp values + per-(row,chunk) partial sums.
__device__ float g_e[BS * OBJ];
__device__ float g_psum[BS * 4];

__device__ __forceinline__ float tanh_fast(float x) {
    float y;
    asm("tanh.approx.f32 %0, %1;" : "=f"(y) : "f"(x));
    return y;
}

// Split fp32 into tf32 hi + tf32 lo (3xTF32 compensation).
__device__ __forceinline__ void tf32_split(float x, uint32_t& hi, uint32_t& lo) {
    asm("cvt.rna.tf32.f32 %0, %1;" : "=r"(hi) : "f"(x));
    float r = x - __uint_as_float(hi);
    asm("cvt.rna.tf32.f32 %0, %1;" : "=r"(lo) : "f"(r));
}

// D += A(tf32) * B(tf32), m16n8k8.
__device__ __forceinline__ void mma_tf32(float* d,
    uint32_t a0, uint32_t a1, uint32_t a2, uint32_t a3,
    uint32_t b0, uint32_t b1)
{
    asm("mma.sync.aligned.m16n8k8.row.col.f32.tf32.tf32.f32 "
        "{%0,%1,%2,%3}, {%4,%5,%6,%7}, {%8,%9}, {%0,%1,%2,%3};"
        : "+f"(d[0]), "+f"(d[1]), "+f"(d[2]), "+f"(d[3])
        : "r"(a0), "r"(a1), "r"(a2), "r"(a3), "r"(b0), "r"(b1));
}

// ---------------- GEMM: tensor-core att_h partials ----------------
// grid (16 n-tiles of 32, 8 k-chunks of 128) = 128 blocks = one wave.
// 256 threads = 8 warps; warp w owns b-rows [16w,16w+16) x all 32 n.
// K chunk staged as 2x64 in smem; 3xTF32 per k-tile for fp32-class accuracy.
// part[c][n][b] = sum_{k in c} h[b][k] * W[n][k].
__global__ __launch_bounds__(256) void gemm_kernel(
    const float* __restrict__ h, const float* __restrict__ W)
{
    __shared__ float h_s[128][68];   // [b][k], pitch 68 (bank = 4*row+col)
    __shared__ float w_s[32][68];    // [n][k]
    const int n0 = blockIdx.x * 32;
    const int k0 = blockIdx.y * 128;
    const int t    = threadIdx.x;
    const int w    = t >> 5;
    const int lane = t & 31;
    const int g    = lane >> 2;      // 0..7
    const int tig  = lane & 3;       // 0..3

    // ---- stage 1 global loads (k0 .. k0+63) ----
    float4 hv[8], wv[2];
    #pragma unroll
    for (int r = 0; r < 8; ++r) {
        int f = t + 256 * r;
        hv[r] = *(const float4*)(h + (f >> 4) * RNN + k0 + (f & 15) * 4);
    }
    #pragma unroll
    for (int r = 0; r < 2; ++r) {
        int f = t + 256 * r;
        wv[r] = *(const float4*)(W + (n0 + (f >> 4)) * RNN + k0 + (f & 15) * 4);
    }
    #pragma unroll
    for (int r = 0; r < 8; ++r) {
        int f = t + 256 * r;
        *(float4*)&h_s[f >> 4][(f & 15) * 4] = hv[r];
    }
    #pragma unroll
    for (int r = 0; r < 2; ++r) {
        int f = t + 256 * r;
        *(float4*)&w_s[f >> 4][(f & 15) * 4] = wv[r];
    }
    __syncthreads();

    // ---- stage 2 global loads issued now (k0+64 .. k0+127) ----
    float4 hv2[8], wv2[2];
    #pragma unroll
    for (int r = 0; r < 8; ++r) {
        int f = t + 256 * r;
        hv2[r] = *(const float4*)(h + (f >> 4) * RNN + k0 + 64 + (f & 15) * 4);
    }
    #pragma unroll
    for (int r = 0; r < 2; ++r) {
        int f = t + 256 * r;
        wv2[r] = *(const float4*)(W + (n0 + (f >> 4)) * RNN + k0 + 64 + (f & 15) * 4);
    }

    float acc[4][4] = {};   // [ntile][mma reg]

    #pragma unroll
    for (int stage = 0; stage < 2; ++stage) {
        if (stage == 1) {
            __syncthreads();
            #pragma unroll
            for (int r = 0; r < 8; ++r) {
                int f = t + 256 * r;
                *(float4*)&h_s[f >> 4][(f & 15) * 4] = hv2[r];
            }
            #pragma unroll
            for (int r = 0; r < 2; ++r) {
                int f = t + 256 * r;
                *(float4*)&w_s[f >> 4][(f & 15) * 4] = wv2[r];
            }
            __syncthreads();
        }

        #pragma unroll
        for (int kt = 0; kt < 8; ++kt) {
            const int kb = kt * 8;
            // A fragment: rows 16w+g(+8), cols kb+tig(+4)  (conflict-free)
            float ar0 = h_s[16*w + g    ][kb + tig];
            float ar1 = h_s[16*w + g + 8][kb + tig];
            float ar2 = h_s[16*w + g    ][kb + tig + 4];
            float ar3 = h_s[16*w + g + 8][kb + tig + 4];
            uint32_t ah0, al0, ah1, al1, ah2, al2, ah3, al3;
            tf32_split(ar0, ah0, al0);
            tf32_split(ar1, ah1, al1);
            tf32_split(ar2, ah2, al2);
            tf32_split(ar3, ah3, al3);

            #pragma unroll
            for (int j = 0; j < 4; ++j) {
                float br0 = w_s[8*j + g][kb + tig];
                float br1 = w_s[8*j + g][kb + tig + 4];
                uint32_t bh0, bl0, bh1, bl1;
                tf32_split(br0, bh0, bl0);
                tf32_split(br1, bh1, bl1);
                mma_tf32(acc[j], ah0, ah1, ah2, ah3, bh0, bh1);  // Ah*Bh
                mma_tf32(acc[j], al0, al1, al2, al3, bh0, bh1);  // Al*Bh
                mma_tf32(acc[j], ah0, ah1, ah2, ah3, bl0, bl1);  // Ah*Bl
            }
        }
    }

    // Epilogue: D[m][n] -> part[n][b]; lanes with equal tig span 8 consecutive
    // b (32B sectors), 4 sectors/warp-store: sector-optimal.
    float* outp = g_part + blockIdx.y * (HID * BS);
    #pragma unroll
    for (int j = 0; j < 4; ++j) {
        int n = n0 + 8 * j + 2 * tig;
        int b = 16 * w + g;
        outp[n       * BS + b]     = acc[j][0];
        outp[(n + 1) * BS + b]     = acc[j][1];
        outp[n       * BS + b + 8] = acc[j][2];
        outp[(n + 1) * BS + b + 8] = acc[j][3];
    }
}

// ---------------- Reduce (PDL) + transpose (R14-proven, KCHUNKS=8) ----------
__global__ __launch_bounds__(1024) void reduce_kernel(
    const float* __restrict__ b_h2att)
{
    __shared__ float tile[8][132];
    const int t  = threadIdx.x;
    const int n0 = blockIdx.x * 8;
    const int nl = t >> 7;            // 0..7
    const int b  = t & 127;

    float bias = b_h2att[n0 + nl];    // independent of gemm
    cudaGridDependencySynchronize();  // wait for gemm grid

    float s = bias;
    #pragma unroll
    for (int c = 0; c < KCHUNKS; ++c)
        s += g_part[c * (HID * BS) + (n0 + nl) * BS + b];
    tile[nl][b] = s;
    __syncthreads();

    const int b2 = t >> 3;            // 0..127
    const int n2 = t & 7;             // 0..7
    g_attht[b2 * HID + n0 + n2] = tile[n2][b2];
}

// ---------------- Scores (PDL): masked exp + chunk psums (R14-proven) -------
__global__ __launch_bounds__(256) void scores_kernel(
    const float* __restrict__ att_feats,
    const float* __restrict__ w_alpha,
    const int*   __restrict__ att_masks)
{
    const int b     = blockIdx.x >> 2;
    const int chunk = blockIdx.x & 3;
    __shared__ float ah[HID];
    __shared__ float wa[HID];
    __shared__ float mf[128];
    __shared__ float wsum[8];
    const int t = threadIdx.x;
    const int w = t >> 5, lane = t & 31;

    const float4* base = (const float4*)(att_feats
                         + (size_t)b * OBJ * HID + (size_t)chunk * 128 * HID);

    // ---- producer-independent prefetches (overlap gemm + reduce) ----
    float wv0 = w_alpha[t], wv1 = w_alpha[t + 256];
    float mv = (t < 128) ? (float)att_masks[b * OBJ + chunk * 128 + t] : 0.f;
    float4 p0[4], p1[4];                       // peeled iter (o = w)
    {
        const float4* r0 = base + w       * (HID / 4);
        const float4* r1 = base + (w + 8) * (HID / 4);
        #pragma unroll
        for (int i = 0; i < 4; ++i) {
            p0[i] = __ldcs(r0 + lane + 32 * i);
            p1[i] = __ldcs(r1 + lane + 32 * i);
        }
    }

    cudaGridDependencySynchronize();           // wait for reduce grid

    wa[t] = wv0; wa[t + 256] = wv1;
    if (t < 128) mf[t] = mv;
    ah[t]       = g_attht[b * HID + t];        // 2KB contiguous, L2-resident
    ah[t + 256] = g_attht[b * HID + t + 256];
    __syncthreads();

    const float4* ah4 = (const float4*)ah;
    const float4* wa4 = (const float4*)wa;

    float esum = 0.f;   // meaningful on lane 0 of each warp

    // ---- peeled first iteration ----
    {
        float s0 = 0.f, s1 = 0.f;
        #pragma unroll
        for (int i = 0; i < 4; ++i) {
            int idx = lane + 32 * i;
            float4 a  = ah4[idx];
            float4 wv = wa4[idx];
            s0 += tanh_fast(p0[i].x + a.x) * wv.x;
            s0 += tanh_fast(p0[i].y + a.y) * wv.y;
            s0 += tanh_fast(p0[i].z + a.z) * wv.z;
            s0 += tanh_fast(p0[i].w + a.w) * wv.w;
            s1 += tanh_fast(p1[i].x + a.x) * wv.x;
            s1 += tanh_fast(p1[i].y + a.y) * wv.y;
            s1 += tanh_fast(p1[i].z + a.z) * wv.z;
            s1 += tanh_fast(p1[i].w + a.w) * wv.w;
        }
        #pragma unroll
        for (int d = 16; d; d >>= 1) {
            s0 += __shfl_xor_sync(0xffffffffu, s0, d);
            s1 += __shfl_xor_sync(0xffffffffu, s1, d);
        }
        if (lane == 0) {
            float e0 = mf[w]     * __expf(s0);
            float e1 = mf[w + 8] * __expf(s1);
            g_e[b * OBJ + chunk * 128 + w]     = e0;
            g_e[b * OBJ + chunk * 128 + w + 8] = e1;
            esum += e0 + e1;
        }
    }

    // ---- remaining iterations ----
    for (int o = w + 16; o < 128; o += 16) {
        const float4* r0 = base + o       * (HID / 4);
        const float4* r1 = base + (o + 8) * (HID / 4);
        float4 f0[4], f1[4];
        #pragma unroll
        for (int i = 0; i < 4; ++i) {
            f0[i] = __ldcs(r0 + lane + 32 * i);
            f1[i] = __ldcs(r1 + lane + 32 * i);
        }
        float s0 = 0.f, s1 = 0.f;
        #pragma unroll
        for (int i = 0; i < 4; ++i) {
            int idx = lane + 32 * i;
            float4 a  = ah4[idx];
            float4 wv = wa4[idx];
            s0 += tanh_fast(f0[i].x + a.x) * wv.x;
            s0 += tanh_fast(f0[i].y + a.y) * wv.y;
            s0 += tanh_fast(f0[i].z + a.z) * wv.z;
            s0 += tanh_fast(f0[i].w + a.w) * wv.w;
            s1 += tanh_fast(f1[i].x + a.x) * wv.x;
            s1 += tanh_fast(f1[i].y + a.y) * wv.y;
            s1 += tanh_fast(f1[i].z + a.z) * wv.z;
            s1 += tanh_fast(f1[i].w + a.w) * wv.w;
        }
        #pragma unroll
        for (int d = 16; d; d >>= 1) {
            s0 += __shfl_xor_sync(0xffffffffu, s0, d);
            s1 += __shfl_xor_sync(0xffffffffu, s1, d);
        }
        if (lane == 0) {
            float e0 = mf[o]     * __expf(s0);
            float e1 = mf[o + 8] * __expf(s1);
            g_e[b * OBJ + chunk * 128 + o]     = e0;
            g_e[b * OBJ + chunk * 128 + o + 8] = e1;
            esum += e0 + e1;
        }
    }

    if (lane == 0) wsum[w] = esum;
    __syncthreads();
    if (t == 0) {
        float p = 0.f;
        #pragma unroll
        for (int i = 0; i < 8; ++i) p += wsum[i];   // fixed order: deterministic
        g_psum[b * 4 + chunk] = p;
    }
}

// ---------------- Normalize (PDL): no reductions, no chains ----------------
__global__ __launch_bounds__(128) void normalize_kernel(float* __restrict__ out)
{
    const int b = blockIdx.x;
    const int t = threadIdx.x;
    cudaGridDependencySynchronize();           // wait for scores grid
    const float inv = 1.f / (g_psum[b*4+0] + g_psum[b*4+1]
                           + g_psum[b*4+2] + g_psum[b*4+3]);
    float4 e = ((const float4*)g_e)[b * (OBJ/4) + t];
    float4 o = make_float4(e.x * inv, e.y * inv, e.z * inv, e.w * inv);
    ((float4*)out)[b * (OBJ/4) + t] = o;
}

static void launch_pdl(void* func, dim3 grid, dim3 block, void** args) {
    cudaLaunchConfig_t cfg = {};
    cfg.gridDim = grid;
    cfg.blockDim = block;
    cfg.dynamicSmemBytes = 0;
    cfg.stream = 0;
    cudaLaunchAttribute attr[1];
    attr[0].id = cudaLaunchAttributeProgrammaticStreamSerialization;
    attr[0].val.programmaticStreamSerializationAllowed = 1;
    cfg.attrs = attr;
    cfg.numAttrs = 1;
    cudaLaunchKernelExC(&cfg, func, args);
}

extern "C" void kernel_launch(void* const* d_in, const int* in_sizes, int n_in,
                              void* d_out, int out_size) {
    const float* h         = (const float*)d_in[0];
    const float* att_feats = (const float*)d_in[1];
    const int*   att_masks = (const int*)  d_in[2];
    const float* W_h2att   = (const float*)d_in[3];
    const float* b_h2att   = (const float*)d_in[4];
    const float* w_alpha   = (const float*)d_in[5];
    // d_in[6] = b_alpha: cancels in softmax, unused.
    float* out = (float*)d_out;

    gemm_kernel<<<dim3(16, 8), 256>>>(h, W_h2att);

    {   // reduce + transpose (PDL)
        void* args[] = {(void*)&b_h2att};
        launch_pdl((void*)reduce_kernel, dim3(64), dim3(1024), args);
    }
    {   // scores (PDL)
        void* args[] = {(void*)&att_feats, (void*)&w_alpha, (void*)&att_masks};
        launch_pdl((void*)scores_kernel, dim3(512), dim3(256), args);
    }
    {   // normalize (PDL)
        void* args[] = {(void*)&out};
        launch_pdl((void*)normalize_kernel, dim3(BS), dim3(128), args);
    }
}